// round 6
// baseline (speedup 1.0000x reference)
#include <cuda_runtime.h>
#include <cstdint>

#define HDIM   512
#define TLEN   2048
#define NBATCH 16
#define CLSZ   8
#define CHUNK_B 272                 // 64-float chunk padded to 272 B (bank-perfect)
#define HBUF_B  (8 * CHUNK_B)       // 2176 B per h buffer

typedef unsigned long long u64;
typedef unsigned int u32;

// ---------------- PTX helpers ----------------
__device__ __forceinline__ u32 smem_u32(const void* p) {
    u32 a;
    asm("{ .reg .u64 t; cvta.to.shared.u64 t, %1; cvt.u32.u64 %0, t; }" : "=r"(a) : "l"(p));
    return a;
}
__device__ __forceinline__ void fma2(u64& d, u64 a, u64 b) {
    asm("fma.rn.f32x2 %0, %1, %2, %0;" : "+l"(d) : "l"(a), "l"(b));
}
__device__ __forceinline__ void add2(u64& d, u64 a, u64 b) {
    asm("add.rn.f32x2 %0, %1, %2;" : "=l"(d) : "l"(a), "l"(b));
}
__device__ __forceinline__ u64 pk2(float lo, float hi) {
    u64 r; asm("mov.b64 %0, {%1, %2};" : "=l"(r) : "f"(lo), "f"(hi)); return r;
}
__device__ __forceinline__ float lo32(u64 v) { return __uint_as_float((u32)(v & 0xffffffffull)); }
__device__ __forceinline__ float hi32(u64 v) { return __uint_as_float((u32)(v >> 32)); }
__device__ __forceinline__ u32 mapa32(u32 a, u32 r) {
    u32 d; asm("mapa.shared::cluster.u32 %0, %1, %2;" : "=r"(d) : "r"(a), "r"(r)); return d;
}
__device__ __forceinline__ void st_async32(u32 ra, u32 v, u32 rb) {
    asm volatile("st.async.shared::cluster.mbarrier::complete_tx::bytes.b32 [%0], %1, [%2];"
                 :: "r"(ra), "r"(v), "r"(rb) : "memory");
}
__device__ __forceinline__ void mbar_init(u32 m, u32 cnt) {
    asm volatile("mbarrier.init.shared.b64 [%0], %1;" :: "r"(m), "r"(cnt) : "memory");
}
__device__ __forceinline__ void mbar_expect_tx(u32 m, u32 bytes) {
    asm volatile("mbarrier.arrive.expect_tx.shared.b64 _, [%0], %1;" :: "r"(m), "r"(bytes) : "memory");
}
__device__ __forceinline__ void mbar_wait_parity(u32 m, u32 parity) {
    asm volatile(
        "{\n\t.reg .pred P;\nLW_%=:\n\t"
        "mbarrier.try_wait.parity.acquire.cluster.shared::cta.b64 P, [%0], %1, 0x989680;\n\t"
        "@!P bra LW_%=;\n\t}"
        :: "r"(m), "r"(parity) : "memory");
}
__device__ __forceinline__ void cluster_sync_() {
    asm volatile("barrier.cluster.arrive.aligned;" ::: "memory");
    asm volatile("barrier.cluster.wait.aligned;" ::: "memory");
}
// tanh(x) = sign(x)*(1-e)/(1+e), e = exp2(-2x/ln2 * ...), ~1e-7 abs err
__device__ __forceinline__ float fast_tanh(float x) {
    float ax = fabsf(x);
    float e;
    asm("ex2.approx.ftz.f32 %0, %1;" : "=f"(e) : "f"(ax * -2.885390082f));
    float r;
    asm("rcp.approx.ftz.f32 %0, %1;" : "=f"(r) : "f"(1.0f + e));
    return copysignf((1.0f - e) * r, x);
}

// ---------------- Phase 1: pre = X @ W_xh + b (M=32768,N=512,K=512), f32x2 ----------------
__global__ __launch_bounds__(256, 2) void pre_gemm(
    const float* __restrict__ X, const float* __restrict__ W,
    const float* __restrict__ bias, float* __restrict__ P)
{
    __shared__ __align__(16) float As[16][130];  // [k][m]
    __shared__ __align__(16) float Bs[16][64];   // [k][n]
    const int tid = threadIdx.x;
    const int tx  = tid & 15;
    const int ty  = tid >> 4;
    const int m0  = blockIdx.x * 128;
    const int n0  = blockIdx.y * 64;
    const int arow = tid >> 1;
    const int ak   = (tid & 1) * 8;
    const int bk   = tid >> 4;
    const int bn   = (tid & 15) * 4;

    u64 acc[4][4];  // [m-pair][n]
    #pragma unroll
    for (int i = 0; i < 4; i++)
        #pragma unroll
        for (int j = 0; j < 4; j++) acc[i][j] = 0ull;

    for (int kb = 0; kb < 32; kb++) {
        const int k0 = kb * 16;
        const float* Xp = X + (m0 + arow) * HDIM + k0 + ak;
        float4 a0 = *(const float4*)Xp;
        float4 a1 = *(const float4*)(Xp + 4);
        float4 bv = *(const float4*)(W + (k0 + bk) * HDIM + n0 + bn);
        As[ak+0][arow] = a0.x; As[ak+1][arow] = a0.y; As[ak+2][arow] = a0.z; As[ak+3][arow] = a0.w;
        As[ak+4][arow] = a1.x; As[ak+5][arow] = a1.y; As[ak+6][arow] = a1.z; As[ak+7][arow] = a1.w;
        *(float4*)&Bs[bk][bn] = bv;
        __syncthreads();
        #pragma unroll
        for (int k = 0; k < 16; k++) {
            float4 rb = *(const float4*)&Bs[k][tx * 4];
            u64 rbb[4];
            rbb[0] = pk2(rb.x, rb.x); rbb[1] = pk2(rb.y, rb.y);
            rbb[2] = pk2(rb.z, rb.z); rbb[3] = pk2(rb.w, rb.w);
            const u64* ap = (const u64*)&As[k][ty * 8];
            #pragma unroll
            for (int i = 0; i < 4; i++) {
                u64 ra = ap[i];
                fma2(acc[i][0], ra, rbb[0]);
                fma2(acc[i][1], ra, rbb[1]);
                fma2(acc[i][2], ra, rbb[2]);
                fma2(acc[i][3], ra, rbb[3]);
            }
        }
        __syncthreads();
    }
    float4 bb = *(const float4*)(bias + n0 + tx * 4);
    #pragma unroll
    for (int i = 0; i < 4; i++) {
        float4 o0, o1;
        o0.x = lo32(acc[i][0]) + bb.x; o1.x = hi32(acc[i][0]) + bb.x;
        o0.y = lo32(acc[i][1]) + bb.y; o1.y = hi32(acc[i][1]) + bb.y;
        o0.z = lo32(acc[i][2]) + bb.z; o1.z = hi32(acc[i][2]) + bb.z;
        o0.w = lo32(acc[i][3]) + bb.w; o1.w = hi32(acc[i][3]) + bb.w;
        *(float4*)&P[(m0 + ty * 8 + 2*i)     * HDIM + n0 + tx * 4] = o0;
        *(float4*)&P[(m0 + ty * 8 + 2*i + 1) * HDIM + n0 + tx * 4] = o1;
    }
}

// ---------------- Phase 2: scan. 1 col/thread, warp-local reduce, hoisted mapa ----------------
__global__ __launch_bounds__(512, 1) __cluster_dims__(CLSZ, 1, 1)
void rnn_scan(const float* __restrict__ Whh, float* __restrict__ out)
{
    __shared__ __align__(16) char hsm[2 * HBUF_B];   // double-buffered padded h
    __shared__ __align__(16) u64 mbar[2];

    const int tid  = threadIdx.x;
    const int wi   = tid >> 5;
    const int lane = tid & 31;
    const int rank  = blockIdx.x & (CLSZ - 1);
    const int batch = blockIdx.x / CLSZ;
    const int cjf  = wi * 4 + (lane & 3);   // this thread's column (0..63 within CTA)
    const int ks   = lane >> 2;             // k-split 0..7 (64 k each)

    // W_hh[:,rank*64+cjf] slice for k in [ks*64, ks*64+64), packed (k,k+1)
    u64 w[32];
    {
        const int j = rank * 64 + cjf;
        const int k0 = ks * 64;
        #pragma unroll
        for (int p = 0; p < 32; p++)
            w[p] = pk2(Whh[(k0 + 2*p) * HDIM + j], Whh[(k0 + 2*p + 1) * HDIM + j]);
    }

    // zero both h buffers (incl. padding)
    for (int i = tid; i < (2 * HBUF_B) / 4; i += 512) ((float*)hsm)[i] = 0.0f;
    const u32 h0a = smem_u32(hsm);
    const u32 mb0 = smem_u32(&mbar[0]);
    if (tid == 0) {
        mbar_init(mb0, 1);
        mbar_init(mb0 + 8, 1);
        asm volatile("fence.mbarrier_init.release.cluster;" ::: "memory");
    }
    __syncthreads();
    cluster_sync_();

    // hoisted DSMEM addresses (buffer 0 / barrier 0; +HBUF_B / +8 for buffer 1)
    u32 dst0[CLSZ], bar0[CLSZ];
    {
        const u32 loc = h0a + (u32)(rank * CHUNK_B + cjf * 4);
        #pragma unroll
        for (int r = 0; r < CLSZ; r++) {
            dst0[r] = mapa32(loc, (u32)r);
            bar0[r] = mapa32(mb0, (u32)r);
        }
    }

    const long base = (long)batch * TLEN * HDIM + rank * 64;
    float preReg = (lane < 4) ? out[base + cjf] : 0.0f;   // pre[b][0][col]

    for (int t = 0; t < TLEN; ++t) {
        const int pb = t & 1;
        const int nb = pb ^ 1;
        if (t > 0) mbar_wait_parity(mb0 + (u32)pb * 8u, (u32)(((t - 2 + pb) >> 1) & 1));

        // matvec partial: col cjf, k in [ks*64, +64). 16x LDS.128, conflict-free.
        const char* hb = hsm + pb * HBUF_B + ks * CHUNK_B;
        u64 a0 = 0ull, a1 = 0ull, a2 = 0ull, a3 = 0ull;
        #pragma unroll
        for (int q = 0; q < 16; q += 2) {
            ulonglong2 h0 = *(const ulonglong2*)(hb + q * 16);
            ulonglong2 h1 = *(const ulonglong2*)(hb + q * 16 + 16);
            fma2(a0, h0.x, w[2*q]);
            fma2(a1, h0.y, w[2*q + 1]);
            fma2(a2, h1.x, w[2*q + 2]);
            fma2(a3, h1.y, w[2*q + 3]);
        }
        u64 t01, t23, tt;
        add2(t01, a0, a1); add2(t23, a2, a3); add2(tt, t01, t23);
        float s = lo32(tt) + hi32(tt);
        // fold 8 k-splits of this column (lanes cjf, cjf+4, ..., cjf+28)
        s += __shfl_down_sync(0xffffffffu, s, 16);
        s += __shfl_down_sync(0xffffffffu, s, 8);
        s += __shfl_down_sync(0xffffffffu, s, 4);

        // all h-buffer reads done before any peer may receive next writes to it
        __syncthreads();

        if (lane < 4) {
            const float hv = fast_tanh(s + preReg);
            if (t + 1 < TLEN) {
                const u32 val  = __float_as_uint(hv);
                const u32 doff = (u32)nb * HBUF_B;
                const u32 boff = (u32)nb * 8u;
                #pragma unroll
                for (int r = 0; r < CLSZ; r++)
                    st_async32(dst0[r] + doff, val, bar0[r] + boff);
                if (tid == 0) mbar_expect_tx(mb0 + boff, CLSZ * 64 * 4);
                out[base + (long)t * HDIM + cjf] = hv;
                preReg = out[base + (long)(t + 1) * HDIM + cjf];  // prefetch
            } else {
                out[base + (long)t * HDIM + cjf] = hv;
            }
        }
    }
    cluster_sync_();
}

// ---------------- launch ----------------
extern "C" void kernel_launch(void* const* d_in, const int* in_sizes, int n_in,
                              void* d_out, int out_size) {
    (void)in_sizes; (void)n_in; (void)out_size;
    const float* x    = (const float*)d_in[0];
    const float* Wxh  = (const float*)d_in[1];
    const float* Whh  = (const float*)d_in[2];
    const float* bias = (const float*)d_in[3];
    float* out = (float*)d_out;   // d_in[4] = A: backward-only, unused

    dim3 g1(NBATCH * TLEN / 128, HDIM / 64);
    pre_gemm<<<g1, 256>>>(x, Wxh, bias, out);     // pre (+bias) into out
    rnn_scan<<<NBATCH * CLSZ, 512>>>(Whh, out);   // in-place scan
}

// round 9
// speedup vs baseline: 1.5603x; 1.5603x over previous
#include <cuda_runtime.h>
#include <cstdint>

#define HDIM   512
#define TLEN   2048
#define NBATCH 16
#define CLSZ   8
#define CHUNK_B 272                 // 64-float chunk padded to 272 B (bank-perfect)
#define HBUF_B  (8 * CHUNK_B)       // 2176 B per h buffer

typedef unsigned long long u64;
typedef unsigned int u32;

// ---------------- PTX helpers ----------------
__device__ __forceinline__ u32 smem_u32(const void* p) {
    u32 a;
    asm("{ .reg .u64 t; cvta.to.shared.u64 t, %1; cvt.u32.u64 %0, t; }" : "=r"(a) : "l"(p));
    return a;
}
__device__ __forceinline__ void fma2(u64& d, u64 a, u64 b) {
    asm("fma.rn.f32x2 %0, %1, %2, %0;" : "+l"(d) : "l"(a), "l"(b));
}
__device__ __forceinline__ void add2(u64& d, u64 a, u64 b) {
    asm("add.rn.f32x2 %0, %1, %2;" : "=l"(d) : "l"(a), "l"(b));
}
__device__ __forceinline__ u64 pk2(float lo, float hi) {
    u64 r; asm("mov.b64 %0, {%1, %2};" : "=l"(r) : "f"(lo), "f"(hi)); return r;
}
__device__ __forceinline__ float lo32(u64 v) { return __uint_as_float((u32)(v & 0xffffffffull)); }
__device__ __forceinline__ float hi32(u64 v) { return __uint_as_float((u32)(v >> 32)); }
__device__ __forceinline__ u32 mapa32(u32 a, u32 r) {
    u32 d; asm("mapa.shared::cluster.u32 %0, %1, %2;" : "=r"(d) : "r"(a), "r"(r)); return d;
}
__device__ __forceinline__ void st_async32(u32 ra, u32 v, u32 rb) {
    asm volatile("st.async.shared::cluster.mbarrier::complete_tx::bytes.b32 [%0], %1, [%2];"
                 :: "r"(ra), "r"(v), "r"(rb) : "memory");
}
__device__ __forceinline__ void mbar_init(u32 m, u32 cnt) {
    asm volatile("mbarrier.init.shared.b64 [%0], %1;" :: "r"(m), "r"(cnt) : "memory");
}
__device__ __forceinline__ void mbar_expect_tx(u32 m, u32 bytes) {
    asm volatile("mbarrier.arrive.expect_tx.shared.b64 _, [%0], %1;" :: "r"(m), "r"(bytes) : "memory");
}
__device__ __forceinline__ void mbar_wait_parity(u32 m, u32 parity) {
    asm volatile(
        "{\n\t.reg .pred P;\nLW_%=:\n\t"
        "mbarrier.try_wait.parity.acquire.cluster.shared::cta.b64 P, [%0], %1, 0x989680;\n\t"
        "@!P bra LW_%=;\n\t}"
        :: "r"(m), "r"(parity) : "memory");
}
__device__ __forceinline__ void cluster_sync_() {
    asm volatile("barrier.cluster.arrive.aligned;" ::: "memory");
    asm volatile("barrier.cluster.wait.aligned;" ::: "memory");
}
// tanh(x) = sign(x)*(1-e)/(1+e), e = exp2(-2x*log2e), ~1e-7 abs err
__device__ __forceinline__ float fast_tanh(float x) {
    float ax = fabsf(x);
    float e;
    asm("ex2.approx.ftz.f32 %0, %1;" : "=f"(e) : "f"(ax * -2.885390082f));
    float r;
    asm("rcp.approx.ftz.f32 %0, %1;" : "=f"(r) : "f"(1.0f + e));
    return copysignf((1.0f - e) * r, x);
}

// ---------------- Phase 1: pre = X @ W_xh + b  (M=32768, N=512, K=512) ----------------
// R1 version (known-good): 128x64 tile, BK=16, 256 threads, 8x4 microtile, plain fp32.
__global__ __launch_bounds__(256) void pre_gemm(
    const float* __restrict__ X, const float* __restrict__ W,
    const float* __restrict__ bias, float* __restrict__ P)
{
    __shared__ __align__(16) float As[16][130];
    __shared__ __align__(16) float Bs[16][64];
    const int tid = threadIdx.x;
    const int tx  = tid & 15;
    const int ty  = tid >> 4;
    const int m0  = blockIdx.x * 128;
    const int n0  = blockIdx.y * 64;
    const int arow = tid >> 1;
    const int ak   = (tid & 1) * 8;
    const int bk   = tid >> 4;
    const int bn   = (tid & 15) * 4;

    float acc[8][4];
    #pragma unroll
    for (int i = 0; i < 8; i++)
        #pragma unroll
        for (int j = 0; j < 4; j++) acc[i][j] = 0.0f;

    for (int kb = 0; kb < 32; kb++) {
        const int k0 = kb * 16;
        const float* Xp = X + (m0 + arow) * HDIM + k0 + ak;
        float4 a0 = *(const float4*)Xp;
        float4 a1 = *(const float4*)(Xp + 4);
        float4 bv = *(const float4*)(W + (k0 + bk) * HDIM + n0 + bn);
        As[ak+0][arow] = a0.x; As[ak+1][arow] = a0.y; As[ak+2][arow] = a0.z; As[ak+3][arow] = a0.w;
        As[ak+4][arow] = a1.x; As[ak+5][arow] = a1.y; As[ak+6][arow] = a1.z; As[ak+7][arow] = a1.w;
        *(float4*)&Bs[bk][bn] = bv;
        __syncthreads();
        #pragma unroll
        for (int k = 0; k < 16; k++) {
            float4 rb = *(const float4*)&Bs[k][tx * 4];
            float ra[8];
            #pragma unroll
            for (int i = 0; i < 4; i++) {
                float2 t2 = *(const float2*)&As[k][ty * 8 + 2 * i];
                ra[2*i] = t2.x; ra[2*i+1] = t2.y;
            }
            #pragma unroll
            for (int i = 0; i < 8; i++) {
                acc[i][0] += ra[i] * rb.x;
                acc[i][1] += ra[i] * rb.y;
                acc[i][2] += ra[i] * rb.z;
                acc[i][3] += ra[i] * rb.w;
            }
        }
        __syncthreads();
    }
    float4 bb = *(const float4*)(bias + n0 + tx * 4);
    #pragma unroll
    for (int i = 0; i < 8; i++) {
        float4 o;
        o.x = acc[i][0] + bb.x; o.y = acc[i][1] + bb.y;
        o.z = acc[i][2] + bb.z; o.w = acc[i][3] + bb.w;
        *(float4*)&P[(m0 + ty * 8 + i) * HDIM + n0 + tx * 4] = o;
    }
}

// ---------------- Phase 2: scan ----------------
// 1 column/thread (64 cols/CTA x 8-way k-split), warp-local 3-shfl reduce.
// No per-step CTA barrier: every warp contains sender lanes, so the mbarrier
// chain (peer wait(t+1) <- all our warps' sends(t) <- each warp's reads(t))
// transitively orders all buffer reuse. mapa recomputed in-loop (register cap
// 128 @512thr; hoisting it spilled in R3 -> 2x regression).
__global__ __launch_bounds__(512, 1) __cluster_dims__(CLSZ, 1, 1)
void rnn_scan(const float* __restrict__ Whh, float* __restrict__ out)
{
    __shared__ __align__(16) char hsm[2 * HBUF_B];
    __shared__ __align__(16) u64 mbar[2];

    const int tid  = threadIdx.x;
    const int wi   = tid >> 5;
    const int lane = tid & 31;
    const int rank  = blockIdx.x & (CLSZ - 1);
    const int batch = blockIdx.x / CLSZ;
    const int cjf  = wi * 4 + (lane & 3);   // column (0..63 within CTA)
    const int ks   = lane >> 2;             // k-split 0..7 (64 k each)

    // W_hh[:, rank*64+cjf] for k in [ks*64, ks*64+64), packed (k,k+1): 32 u64
    u64 w[32];
    {
        const int j = rank * 64 + cjf;
        const int k0 = ks * 64;
        #pragma unroll
        for (int p = 0; p < 32; p++)
            w[p] = pk2(Whh[(k0 + 2*p) * HDIM + j], Whh[(k0 + 2*p + 1) * HDIM + j]);
    }

    for (int i = tid; i < (2 * HBUF_B) / 4; i += 512) ((float*)hsm)[i] = 0.0f;
    const u32 h0a = smem_u32(hsm);
    const u32 mb0 = smem_u32(&mbar[0]);
    if (tid == 0) {
        mbar_init(mb0, 1);
        mbar_init(mb0 + 8, 1);
        asm volatile("fence.mbarrier_init.release.cluster;" ::: "memory");
    }
    __syncthreads();
    cluster_sync_();

    const long base = (long)batch * TLEN * HDIM + rank * 64;
    float preReg = (lane < 4) ? out[base + cjf] : 0.0f;     // pre[b][0][col]
    const u32 locd = h0a + (u32)(rank * CHUNK_B + cjf * 4); // my value's offset in buffer 0

    for (int t = 0; t < TLEN; ++t) {
        const int pb = t & 1;
        const int nb = pb ^ 1;
        if (t > 0) mbar_wait_parity(mb0 + (u32)pb * 8u, (u32)(((t - 2 + pb) >> 1) & 1));

        // matvec partial: col cjf, k in [ks*64, +64). 8x LDS.128, conflict-free.
        const char* hb = hsm + pb * HBUF_B + ks * CHUNK_B;
        u64 a0 = 0ull, a1 = 0ull, a2 = 0ull, a3 = 0ull;
        #pragma unroll
        for (int q = 0; q < 16; q += 2) {
            ulonglong2 h0 = *(const ulonglong2*)(hb + q * 16);
            ulonglong2 h1 = *(const ulonglong2*)(hb + q * 16 + 16);
            fma2(a0, h0.x, w[2*q]);
            fma2(a1, h0.y, w[2*q + 1]);
            fma2(a2, h1.x, w[2*q + 2]);
            fma2(a3, h1.y, w[2*q + 3]);
        }
        u64 t01, t23, tt;
        add2(t01, a0, a1); add2(t23, a2, a3); add2(tt, t01, t23);
        float s = lo32(tt) + hi32(tt);
        s += __shfl_down_sync(0xffffffffu, s, 16);
        s += __shfl_down_sync(0xffffffffu, s, 8);
        s += __shfl_down_sync(0xffffffffu, s, 4);

        if (lane < 4) {
            const float hv = fast_tanh(s + preReg);
            if (t + 1 < TLEN) {
                const u32 val  = __float_as_uint(hv);
                const u32 dloc = locd + (u32)nb * HBUF_B;
                const u32 bloc = mb0 + (u32)nb * 8u;
                if (tid == 0) mbar_expect_tx(bloc, CLSZ * 64 * 4);
                #pragma unroll
                for (int r = 0; r < CLSZ; r++)
                    st_async32(mapa32(dloc, (u32)r), val, mapa32(bloc, (u32)r));
                out[base + (long)t * HDIM + cjf] = hv;
                preReg = out[base + (long)(t + 1) * HDIM + cjf];  // prefetch
            } else {
                out[base + (long)t * HDIM + cjf] = hv;
            }
        }
    }
    cluster_sync_();
}

// ---------------- launch ----------------
extern "C" void kernel_launch(void* const* d_in, const int* in_sizes, int n_in,
                              void* d_out, int out_size) {
    (void)in_sizes; (void)n_in; (void)out_size;
    const float* x    = (const float*)d_in[0];
    const float* Wxh  = (const float*)d_in[1];
    const float* Whh  = (const float*)d_in[2];
    const float* bias = (const float*)d_in[3];
    float* out = (float*)d_out;   // d_in[4] = A: backward-only, unused

    dim3 g1(NBATCH * TLEN / 128, HDIM / 64);
    pre_gemm<<<g1, 256>>>(x, Wxh, bias, out);     // pre (+bias) into out
    rnn_scan<<<NBATCH * CLSZ, 512>>>(Whh, out);   // in-place scan
}

// round 11
// speedup vs baseline: 2.2808x; 1.4618x over previous
#include <cuda_runtime.h>
#include <cstdint>

#define HDIM   512
#define TLEN   2048
#define NBATCH 16
#define CLSZ   8
#define NCLUSTER (NBATCH / 2)       // 8 clusters, 2 batches each

typedef unsigned long long u64;
typedef unsigned int u32;

// ---------------- PTX helpers ----------------
__device__ __forceinline__ u32 smem_u32(const void* p) {
    u32 a;
    asm("{ .reg .u64 t; cvta.to.shared.u64 t, %1; cvt.u32.u64 %0, t; }" : "=r"(a) : "l"(p));
    return a;
}
__device__ __forceinline__ void fma2(u64& d, u64 a, u64 b) {
    asm("fma.rn.f32x2 %0, %1, %2, %0;" : "+l"(d) : "l"(a), "l"(b));
}
__device__ __forceinline__ u64 pk2(float lo, float hi) {
    u64 r; asm("mov.b64 %0, {%1, %2};" : "=l"(r) : "f"(lo), "f"(hi)); return r;
}
__device__ __forceinline__ float lo32(u64 v) { return __uint_as_float((u32)(v & 0xffffffffull)); }
__device__ __forceinline__ float hi32(u64 v) { return __uint_as_float((u32)(v >> 32)); }
__device__ __forceinline__ u32 mapa32(u32 a, u32 r) {
    u32 d; asm("mapa.shared::cluster.u32 %0, %1, %2;" : "=r"(d) : "r"(a), "r"(r)); return d;
}
__device__ __forceinline__ void st_async32(u32 ra, u32 v, u32 rb) {
    asm volatile("st.async.shared::cluster.mbarrier::complete_tx::bytes.b32 [%0], %1, [%2];"
                 :: "r"(ra), "r"(v), "r"(rb) : "memory");
}
__device__ __forceinline__ void mbar_init(u32 m, u32 cnt) {
    asm volatile("mbarrier.init.shared.b64 [%0], %1;" :: "r"(m), "r"(cnt) : "memory");
}
__device__ __forceinline__ void mbar_expect_tx(u32 m, u32 bytes) {
    asm volatile("mbarrier.arrive.expect_tx.shared.b64 _, [%0], %1;" :: "r"(m), "r"(bytes) : "memory");
}
__device__ __forceinline__ void mbar_wait_parity(u32 m, u32 parity) {
    asm volatile(
        "{\n\t.reg .pred P;\nLW_%=:\n\t"
        "mbarrier.try_wait.parity.acquire.cluster.shared::cta.b64 P, [%0], %1, 0x989680;\n\t"
        "@!P bra LW_%=;\n\t}"
        :: "r"(m), "r"(parity) : "memory");
}
__device__ __forceinline__ void cluster_sync_() {
    asm volatile("barrier.cluster.arrive.aligned;" ::: "memory");
    asm volatile("barrier.cluster.wait.aligned;" ::: "memory");
}
__device__ __forceinline__ void bar_arrive(int id) {
    asm volatile("bar.arrive %0, 512;" :: "r"(id) : "memory");
}
__device__ __forceinline__ void bar_sync_named(int id) {
    asm volatile("bar.sync %0, 512;" :: "r"(id) : "memory");
}
// tanh(x) = sign(x)*(1-e)/(1+e), e = exp2(-2x*log2e), ~1e-7 abs err
__device__ __forceinline__ float fast_tanh(float x) {
    float ax = fabsf(x);
    float e;
    asm("ex2.approx.ftz.f32 %0, %1;" : "=f"(e) : "f"(ax * -2.885390082f));
    float r;
    asm("rcp.approx.ftz.f32 %0, %1;" : "=f"(r) : "f"(1.0f + e));
    return copysignf((1.0f - e) * r, x);
}

// ---------------- Phase 1: pre = X @ W_xh + b  (M=32768, N=512, K=512) ----------------
// R1 version (known-good): 128x64 tile, BK=16, 256 threads, 8x4 microtile, plain fp32.
__global__ __launch_bounds__(256) void pre_gemm(
    const float* __restrict__ X, const float* __restrict__ W,
    const float* __restrict__ bias, float* __restrict__ P)
{
    __shared__ __align__(16) float As[16][130];
    __shared__ __align__(16) float Bs[16][64];
    const int tid = threadIdx.x;
    const int tx  = tid & 15;
    const int ty  = tid >> 4;
    const int m0  = blockIdx.x * 128;
    const int n0  = blockIdx.y * 64;
    const int arow = tid >> 1;
    const int ak   = (tid & 1) * 8;
    const int bk   = tid >> 4;
    const int bn   = (tid & 15) * 4;

    float acc[8][4];
    #pragma unroll
    for (int i = 0; i < 8; i++)
        #pragma unroll
        for (int j = 0; j < 4; j++) acc[i][j] = 0.0f;

    for (int kb = 0; kb < 32; kb++) {
        const int k0 = kb * 16;
        const float* Xp = X + (m0 + arow) * HDIM + k0 + ak;
        float4 a0 = *(const float4*)Xp;
        float4 a1 = *(const float4*)(Xp + 4);
        float4 bv = *(const float4*)(W + (k0 + bk) * HDIM + n0 + bn);
        As[ak+0][arow] = a0.x; As[ak+1][arow] = a0.y; As[ak+2][arow] = a0.z; As[ak+3][arow] = a0.w;
        As[ak+4][arow] = a1.x; As[ak+5][arow] = a1.y; As[ak+6][arow] = a1.z; As[ak+7][arow] = a1.w;
        *(float4*)&Bs[bk][bn] = bv;
        __syncthreads();
        #pragma unroll
        for (int k = 0; k < 16; k++) {
            float4 rb = *(const float4*)&Bs[k][tx * 4];
            float ra[8];
            #pragma unroll
            for (int i = 0; i < 4; i++) {
                float2 t2 = *(const float2*)&As[k][ty * 8 + 2 * i];
                ra[2*i] = t2.x; ra[2*i+1] = t2.y;
            }
            #pragma unroll
            for (int i = 0; i < 8; i++) {
                acc[i][0] += ra[i] * rb.x;
                acc[i][1] += ra[i] * rb.y;
                acc[i][2] += ra[i] * rb.z;
                acc[i][3] += ra[i] * rb.w;
            }
        }
        __syncthreads();
    }
    float4 bb = *(const float4*)(bias + n0 + tx * 4);
    #pragma unroll
    for (int i = 0; i < 8; i++) {
        float4 o;
        o.x = acc[i][0] + bb.x; o.y = acc[i][1] + bb.y;
        o.z = acc[i][2] + bb.z; o.w = acc[i][3] + bb.w;
        *(float4*)&P[(m0 + ty * 8 + i) * HDIM + n0 + tx * 4] = o;
    }
}

// ---------------- Phase 2: scan, 2 batches per cluster ----------------
// R1 skeleton (jg/kc decomposition, w[4][8] in regs, smem partial reduce) but:
//  - each cluster runs batches 2c and 2c+1 with the SAME weight registers
//  - named bar.arrive/bar.sync: warps 0-1 finish A, warps 2-3 finish B,
//    producers never block on finish work
//  - one combined mbarrier phase per step (expect_tx = 4096 = A+B sends)
//  - fast_tanh + tree reduction
__global__ __launch_bounds__(512, 1) __cluster_dims__(CLSZ, 1, 1)
void rnn_scan(const float* __restrict__ Whh, float* __restrict__ out)
{
    __shared__ __align__(16) float hA[2][HDIM];
    __shared__ __align__(16) float hB[2][HDIM];
    __shared__ __align__(16) float redA[16][64];
    __shared__ __align__(16) float redB[16][64];
    __shared__ __align__(16) u64 mbar[2];

    const int tid  = threadIdx.x;
    const int wi   = tid >> 5;
    const int lane = tid & 31;
    const int rank = blockIdx.x & (CLSZ - 1);
    const int cl   = blockIdx.x / CLSZ;          // cluster id 0..7
    const int jg   = tid & 15;                   // 4-col group
    const int kc   = tid >> 4;                   // 16-k chunk (0..31)

    // W_hh[:, rank*64 + jg*4 .. +4) for k in [kc*16, +16), packed (k,k+1): 32 u64
    u64 w[4][8];
    {
        const int j0 = rank * 64 + jg * 4;
        const int kb = kc * 16;
        #pragma unroll
        for (int p = 0; p < 8; p++) {
            float4 l4 = *(const float4*)(Whh + (kb + 2*p)     * HDIM + j0);
            float4 h4 = *(const float4*)(Whh + (kb + 2*p + 1) * HDIM + j0);
            w[0][p] = pk2(l4.x, h4.x);
            w[1][p] = pk2(l4.y, h4.y);
            w[2][p] = pk2(l4.z, h4.z);
            w[3][p] = pk2(l4.w, h4.w);
        }
    }

    hA[0][tid] = 0.0f; hA[1][tid] = 0.0f;
    hB[0][tid] = 0.0f; hB[1][tid] = 0.0f;
    const u32 hAa = smem_u32(&hA[0][0]);
    const u32 hBa = smem_u32(&hB[0][0]);
    const u32 mb0 = smem_u32(&mbar[0]);
    if (tid == 0) {
        mbar_init(mb0, 1);
        mbar_init(mb0 + 8, 1);
        asm volatile("fence.mbarrier_init.release.cluster;" ::: "memory");
    }
    __syncthreads();
    cluster_sync_();

    const long baseA = (long)(2 * cl)     * TLEN * HDIM + rank * 64;
    const long baseB = (long)(2 * cl + 1) * TLEN * HDIM + rank * 64;
    float preA = 0.0f, preB = 0.0f;
    if (tid < 64)                 preA = out[baseA + tid];         // pre[2c][0][col]
    else if (tid < 128)           preB = out[baseB + (tid - 64)];  // pre[2c+1][0][col]

    for (int t = 0; t < TLEN; ++t) {
        const int pb = t & 1;
        const int nb = pb ^ 1;
        if (t > 0) mbar_wait_parity(mb0 + (u32)pb * 8u, (u32)(((t - 2 + pb) >> 1) & 1));

        // ---- matvec A ----
        {
            const u64* hp = (const u64*)&hA[pb][kc * 16];
            u64 a0 = 0ull, a1 = 0ull, a2 = 0ull, a3 = 0ull;
            #pragma unroll
            for (int p = 0; p < 8; p++) {
                u64 hv = hp[p];
                fma2(a0, hv, w[0][p]); fma2(a1, hv, w[1][p]);
                fma2(a2, hv, w[2][p]); fma2(a3, hv, w[3][p]);
            }
            float s0 = lo32(a0) + hi32(a0);
            float s1 = lo32(a1) + hi32(a1);
            float s2 = lo32(a2) + hi32(a2);
            float s3 = lo32(a3) + hi32(a3);
            s0 += __shfl_down_sync(0xffffffffu, s0, 16);
            s1 += __shfl_down_sync(0xffffffffu, s1, 16);
            s2 += __shfl_down_sync(0xffffffffu, s2, 16);
            s3 += __shfl_down_sync(0xffffffffu, s3, 16);
            if (lane < 16) {
                float4 v; v.x = s0; v.y = s1; v.z = s2; v.w = s3;
                *(float4*)&redA[wi][jg * 4] = v;
            }
        }
        if (wi < 2) {
            bar_sync_named(1);
            // ---- finish A (warps 0-1, col = tid) ----
            float p0 = redA[0][tid],  p1 = redA[1][tid],  p2 = redA[2][tid],  p3 = redA[3][tid];
            float p4 = redA[4][tid],  p5 = redA[5][tid],  p6 = redA[6][tid],  p7 = redA[7][tid];
            float p8 = redA[8][tid],  p9 = redA[9][tid],  pa = redA[10][tid], pc = redA[11][tid];
            float pd = redA[12][tid], pe = redA[13][tid], pf = redA[14][tid], pg = redA[15][tid];
            float sum = (((p0+p1)+(p2+p3)) + ((p4+p5)+(p6+p7)))
                      + (((p8+p9)+(pa+pc)) + ((pd+pe)+(pf+pg)));
            const float hv = fast_tanh(sum + preA);
            out[baseA + (long)t * HDIM + tid] = hv;
            if (t + 1 < TLEN) {
                preA = out[baseA + (long)(t + 1) * HDIM + tid];
                const u32 val  = __float_as_uint(hv);
                const u32 dloc = hAa + (u32)nb * (HDIM * 4) + (u32)(rank * 64 + tid) * 4;
                const u32 bloc = mb0 + (u32)nb * 8u;
                if (tid == 0) mbar_expect_tx(bloc, 2 * CLSZ * 64 * 4);   // A+B = 4096 B
                #pragma unroll
                for (int r = 0; r < CLSZ; r++)
                    st_async32(mapa32(dloc, (u32)r), val, mapa32(bloc, (u32)r));
            }
        } else {
            bar_arrive(1);
        }

        // ---- matvec B (all warps; warps 0-1 join after finishing A) ----
        {
            const u64* hp = (const u64*)&hB[pb][kc * 16];
            u64 a0 = 0ull, a1 = 0ull, a2 = 0ull, a3 = 0ull;
            #pragma unroll
            for (int p = 0; p < 8; p++) {
                u64 hv = hp[p];
                fma2(a0, hv, w[0][p]); fma2(a1, hv, w[1][p]);
                fma2(a2, hv, w[2][p]); fma2(a3, hv, w[3][p]);
            }
            float s0 = lo32(a0) + hi32(a0);
            float s1 = lo32(a1) + hi32(a1);
            float s2 = lo32(a2) + hi32(a2);
            float s3 = lo32(a3) + hi32(a3);
            s0 += __shfl_down_sync(0xffffffffu, s0, 16);
            s1 += __shfl_down_sync(0xffffffffu, s1, 16);
            s2 += __shfl_down_sync(0xffffffffu, s2, 16);
            s3 += __shfl_down_sync(0xffffffffu, s3, 16);
            if (lane < 16) {
                float4 v; v.x = s0; v.y = s1; v.z = s2; v.w = s3;
                *(float4*)&redB[wi][jg * 4] = v;
            }
        }
        if (wi == 2 || wi == 3) {
            bar_sync_named(2);
            // ---- finish B (warps 2-3, col = tid - 64) ----
            const int c = tid - 64;
            float p0 = redB[0][c],  p1 = redB[1][c],  p2 = redB[2][c],  p3 = redB[3][c];
            float p4 = redB[4][c],  p5 = redB[5][c],  p6 = redB[6][c],  p7 = redB[7][c];
            float p8 = redB[8][c],  p9 = redB[9][c],  pa = redB[10][c], pc = redB[11][c];
            float pd = redB[12][c], pe = redB[13][c], pf = redB[14][c], pg = redB[15][c];
            float sum = (((p0+p1)+(p2+p3)) + ((p4+p5)+(p6+p7)))
                      + (((p8+p9)+(pa+pc)) + ((pd+pe)+(pf+pg)));
            const float hv = fast_tanh(sum + preB);
            out[baseB + (long)t * HDIM + c] = hv;
            if (t + 1 < TLEN) {
                preB = out[baseB + (long)(t + 1) * HDIM + c];
                const u32 val  = __float_as_uint(hv);
                const u32 dloc = hBa + (u32)nb * (HDIM * 4) + (u32)(rank * 64 + c) * 4;
                const u32 bloc = mb0 + (u32)nb * 8u;
                #pragma unroll
                for (int r = 0; r < CLSZ; r++)
                    st_async32(mapa32(dloc, (u32)r), val, mapa32(bloc, (u32)r));
            }
        } else {
            bar_arrive(2);
        }
    }
    cluster_sync_();
}

// ---------------- launch ----------------
extern "C" void kernel_launch(void* const* d_in, const int* in_sizes, int n_in,
                              void* d_out, int out_size) {
    (void)in_sizes; (void)n_in; (void)out_size;
    const float* x    = (const float*)d_in[0];
    const float* Wxh  = (const float*)d_in[1];
    const float* Whh  = (const float*)d_in[2];
    const float* bias = (const float*)d_in[3];
    float* out = (float*)d_out;   // d_in[4] = A: backward-only, unused

    dim3 g1(NBATCH * TLEN / 128, HDIM / 64);
    pre_gemm<<<g1, 256>>>(x, Wxh, bias, out);            // pre (+bias) into out
    rnn_scan<<<NCLUSTER * CLSZ, 512>>>(Whh, out);        // in-place scan, 2 batches/cluster
}